// round 5
// baseline (speedup 1.0000x reference)
#include <cuda_runtime.h>
#include <math.h>

// AttFusion single-pass: out[g,c,s] = sum_m softmax_m(<x0,xm>_c/16) * x[m,c,s]
// x: [28, 256, 8448] fp32; out: [8, 256, 8448] fp32.
//
// R5: block = 1024 threads = (256 channels x 4 float4 parts), 16 s-positions.
// Thread (c, part) loads n float4s ONCE, keeps them in registers across the
// softmax, then writes the weighted sum. Warp = 8 channels x 4 parts: each
// LDG.128/STG.128 covers 8 aligned 64B segments (full sectors). Reduction
// over c: 3 warp shuffles + 10KB smem across 32 warps. DRAM traffic = 311MB.

#define C_DIM   256
#define S_DIM   8448            // 48*176, divisible by 16
#define T_POS   16              // s positions per block (4 float4 parts)
#define N_MAX   5
#define N_GROUP 8

__device__ __constant__ int c_off[N_GROUP] = {0, 2, 5, 9, 14, 17, 19, 23};
__device__ __constant__ int c_len[N_GROUP] = {2, 3, 4, 5, 3, 2, 4, 5};

__global__ __launch_bounds__(1024, 1)
void attfusion_kernel(const float* __restrict__ x, float* __restrict__ out) {
    __shared__ float red[N_MAX][32][4][4];   // [m][warp][part][j] = 10 KB
    __shared__ float wsm[N_MAX][T_POS];      // softmax weights

    const int g    = blockIdx.y;
    const int n    = c_len[g];
    const int off  = c_off[g];
    const int s0   = blockIdx.x * T_POS;
    const int tid  = threadIdx.x;
    const int part = tid & 3;                // which float4 of the 16 positions
    const int c    = tid >> 2;               // channel 0..255
    const int lane = tid & 31;               // = (c&7)*4 + part
    const int warp = tid >> 5;

    const size_t mstride = (size_t)C_DIM * S_DIM;

    // ---- Load: n independent float4s, kept in registers end-to-end ----
    const float* xg = x + (size_t)(off * C_DIM + c) * S_DIM + s0 + part * 4;
    float4 xv[N_MAX];
#pragma unroll
    for (int m = 0; m < N_MAX; m++)
        if (m < n)
            xv[m] = *reinterpret_cast<const float4*>(xg + m * mstride);

    // ---- Per-channel products, reduce over the warp's 8 channels ----
    // c_local occupies lane bits 2..4 -> shuffle strides 4, 8, 16.
    float p[N_MAX][4];
#pragma unroll
    for (int m = 0; m < N_MAX; m++) {
        if (m < n) {
            p[m][0] = xv[0].x * xv[m].x;
            p[m][1] = xv[0].y * xv[m].y;
            p[m][2] = xv[0].z * xv[m].z;
            p[m][3] = xv[0].w * xv[m].w;
#pragma unroll
            for (int d = 4; d <= 16; d <<= 1) {
#pragma unroll
                for (int j = 0; j < 4; j++)
                    p[m][j] += __shfl_down_sync(0xffffffffu, p[m][j], d);
            }
        }
    }
    if (lane < 4) {                          // lane == part for these lanes
#pragma unroll
        for (int m = 0; m < N_MAX; m++)
            if (m < n)
                *reinterpret_cast<float4*>(&red[m][warp][lane][0]) =
                    make_float4(p[m][0], p[m][1], p[m][2], p[m][3]);
    }
    __syncthreads();

    // ---- Cross-warp reduce + softmax: one thread per s position ----
    if (tid < T_POS) {
        const int pp = tid >> 2, jj = tid & 3;
        float d[N_MAX];
#pragma unroll
        for (int m = 0; m < N_MAX; m++) {
            if (m < n) {
                float a = 0.0f;
#pragma unroll
                for (int w = 0; w < 32; w++) a += red[m][w][pp][jj];
                d[m] = a * 0.0625f;          // 1/sqrt(256)
            } else {
                d[m] = -1e30f;
            }
        }
        float mx = d[0];
#pragma unroll
        for (int m = 1; m < N_MAX; m++) mx = fmaxf(mx, d[m]);
        float e[N_MAX], sumv = 0.0f;
#pragma unroll
        for (int m = 0; m < N_MAX; m++)
            if (m < n) { e[m] = __expf(d[m] - mx); sumv += e[m]; }
        const float inv = 1.0f / sumv;
#pragma unroll
        for (int m = 0; m < N_MAX; m++)
            if (m < n) wsm[m][tid] = e[m] * inv;
    }
    __syncthreads();

    // ---- Weighted sum from registers, single float4 store ----
    float4 acc = make_float4(0.f, 0.f, 0.f, 0.f);
#pragma unroll
    for (int m = 0; m < N_MAX; m++) {
        if (m < n) {
            const float4 wv = *reinterpret_cast<const float4*>(&wsm[m][part * 4]);
            acc.x += wv.x * xv[m].x;
            acc.y += wv.y * xv[m].y;
            acc.z += wv.z * xv[m].z;
            acc.w += wv.w * xv[m].w;
        }
    }
    float* og = out + (size_t)(g * C_DIM + c) * S_DIM + s0 + part * 4;
    *reinterpret_cast<float4*>(og) = acc;
}

extern "C" void kernel_launch(void* const* d_in, const int* in_sizes, int n_in,
                              void* d_out, int out_size) {
    const float* x = (const float*)d_in[0];
    float* out = (float*)d_out;

    dim3 grid(S_DIM / T_POS, N_GROUP);       // 528 x 8 = 4224 blocks
    attfusion_kernel<<<grid, 1024>>>(x, out);
}

// round 6
// speedup vs baseline: 1.6053x; 1.6053x over previous
#include <cuda_runtime.h>
#include <math.h>

// AttFusion: out[g,c,s] = sum_m softmax_m(<x0,xm>_c / 16) * x[m,c,s]
// x: [28, 256, 8448] fp32; out: [8, 256, 8448] fp32.
//
// R6: two-pass streaming like R4 (6.3 TB/s) but T_POS=32 so the per-block
// slab is 164 KB and pass-2 re-reads hit L2 (reuse window < 126 MB), cutting
// DRAM traffic toward the 311 MB floor. Warp = 4 channel rows x 8 pos-lanes:
// every LDG.128/STG.128 covers exactly 4 full 128B lines.

#define C_DIM   256
#define S_DIM   8448            // 48*176, divisible by 32
#define T_POS   32              // s positions per block
#define N_MAX   5
#define N_GROUP 8
#define NWARPS  8
#define C_PER_W 32              // channels per warp (4 rows x 8 iters)

__device__ __constant__ int c_off[N_GROUP] = {0, 2, 5, 9, 14, 17, 19, 23};
__device__ __constant__ int c_len[N_GROUP] = {2, 3, 4, 5, 3, 2, 4, 5};

__global__ __launch_bounds__(256, 4)
void attfusion_kernel(const float* __restrict__ x, float* __restrict__ out) {
    __shared__ float red[N_MAX][NWARPS][T_POS];  // 5 KB partial dots
    __shared__ float wsm[N_MAX][T_POS];          // softmax weights

    const int g    = blockIdx.y;
    const int n    = c_len[g];
    const int off  = c_off[g];
    const int s0   = blockIdx.x * T_POS;
    const int tid  = threadIdx.x;
    const int lane = tid & 31;
    const int warp = tid >> 5;
    const int lo3  = lane & 7;               // position octet: covers 4*lo3..4*lo3+3
    const int rowg = lane >> 3;               // channel sub-row 0..3
    const int c0   = warp * C_PER_W;

    const size_t mstride = (size_t)C_DIM * S_DIM;
    const float* xb = x + (size_t)(off * C_DIM + c0 + rowg) * S_DIM + s0 + lo3 * 4;

    // ---- Pass 1: partial dots over this thread's 8 channels ----
    float p[N_MAX][4];
#pragma unroll
    for (int m = 0; m < N_MAX; m++)
#pragma unroll
        for (int j = 0; j < 4; j++) p[m][j] = 0.0f;

    {
        const float* ptr = xb;
#pragma unroll 2
        for (int kk = 0; kk < 8; kk++) {       // channels c0 + rowg + 4*kk
            float4 xv[N_MAX];
#pragma unroll
            for (int m = 0; m < N_MAX; m++)
                if (m < n)
                    xv[m] = *reinterpret_cast<const float4*>(ptr + m * mstride);
#pragma unroll
            for (int m = 0; m < N_MAX; m++) {
                if (m < n) {
                    p[m][0] += xv[0].x * xv[m].x;
                    p[m][1] += xv[0].y * xv[m].y;
                    p[m][2] += xv[0].z * xv[m].z;
                    p[m][3] += xv[0].w * xv[m].w;
                }
            }
            ptr += 4 * S_DIM;
        }
    }

    // combine the 4 channel sub-rows within the warp (rowg = lane bits 3-4)
#pragma unroll
    for (int m = 0; m < N_MAX; m++) {
        if (m < n) {
#pragma unroll
            for (int j = 0; j < 4; j++) {
                p[m][j] += __shfl_down_sync(0xffffffffu, p[m][j], 16);
                p[m][j] += __shfl_down_sync(0xffffffffu, p[m][j], 8);
            }
        }
    }
    if (rowg == 0) {                           // lanes 0..7 hold the sums
#pragma unroll
        for (int m = 0; m < N_MAX; m++)
            if (m < n)
                *reinterpret_cast<float4*>(&red[m][warp][lo3 * 4]) =
                    make_float4(p[m][0], p[m][1], p[m][2], p[m][3]);
    }
    __syncthreads();

    // ---- Cross-warp reduce + softmax: one thread per s position ----
    if (tid < T_POS) {
        float d[N_MAX];
#pragma unroll
        for (int m = 0; m < N_MAX; m++) {
            if (m < n) {
                float a = 0.0f;
#pragma unroll
                for (int w = 0; w < NWARPS; w++) a += red[m][w][tid];
                d[m] = a * 0.0625f;            // 1/sqrt(256)
            } else {
                d[m] = -1e30f;
            }
        }
        float mx = d[0];
#pragma unroll
        for (int m = 1; m < N_MAX; m++) mx = fmaxf(mx, d[m]);
        float e[N_MAX], sumv = 0.0f;
#pragma unroll
        for (int m = 0; m < N_MAX; m++)
            if (m < n) { e[m] = __expf(d[m] - mx); sumv += e[m]; }
        const float inv = 1.0f / sumv;
#pragma unroll
        for (int m = 0; m < N_MAX; m++)
            if (m < n) wsm[m][tid] = e[m] * inv;
    }
    __syncthreads();

    // ---- Pass 2: weighted sum. Slab is L2-hot (164 KB, short reuse) ----
    float4 wv[N_MAX];
#pragma unroll
    for (int m = 0; m < N_MAX; m++)
        if (m < n)
            wv[m] = *reinterpret_cast<const float4*>(&wsm[m][lo3 * 4]);

    {
        const float* ptr = xb;
        float* optr = out + (size_t)(g * C_DIM + c0 + rowg) * S_DIM + s0 + lo3 * 4;
#pragma unroll 2
        for (int kk = 0; kk < 8; kk++) {
            float4 xv[N_MAX];
#pragma unroll
            for (int m = 0; m < N_MAX; m++)
                if (m < n)
                    xv[m] = *reinterpret_cast<const float4*>(ptr + m * mstride);
            float4 acc = make_float4(0.f, 0.f, 0.f, 0.f);
#pragma unroll
            for (int m = 0; m < N_MAX; m++) {
                if (m < n) {
                    acc.x += wv[m].x * xv[m].x;
                    acc.y += wv[m].y * xv[m].y;
                    acc.z += wv[m].z * xv[m].z;
                    acc.w += wv[m].w * xv[m].w;
                }
            }
            *reinterpret_cast<float4*>(optr) = acc;
            ptr  += 4 * S_DIM;
            optr += 4 * S_DIM;
        }
    }
}

extern "C" void kernel_launch(void* const* d_in, const int* in_sizes, int n_in,
                              void* d_out, int out_size) {
    const float* x = (const float*)d_in[0];
    float* out = (float*)d_out;

    dim3 grid(S_DIM / T_POS, N_GROUP);         // 264 x 8 = 2112 blocks
    attfusion_kernel<<<grid, 256>>>(x, out);
}